// round 1
// baseline (speedup 1.0000x reference)
#include <cuda_runtime.h>
#include <math.h>

#define BATCH 2
#define SEQN 2048
#define SEQM 2048
#define DIM 1024
#define HEADS 16
#define DH 64
#define ATT_SCALE 0.125f
#define LN_EPS 1e-5f

// ---------------- scratch (static device memory; no allocation) ----------------
__device__ float g_xn[BATCH * SEQN * DIM];   // layernormed x
__device__ float g_cn[BATCH * SEQM * DIM];   // layernormed context
__device__ float g_q [BATCH * SEQN * DIM];
__device__ float g_k [BATCH * SEQM * DIM];
__device__ float g_v [BATCH * SEQM * DIM];
__device__ float g_ao[BATCH * SEQN * DIM];   // attention output (b, n, h*d)

// ---------------- LayerNorm: one block per row ----------------
__global__ __launch_bounds__(256) void ln_kernel(
    const float* __restrict__ x, const float* __restrict__ ctx,
    const float* __restrict__ w, const float* __restrict__ b,
    float* __restrict__ xn, float* __restrict__ cn)
{
    int row = blockIdx.x;                // 0 .. 2*B*SEQN-1
    const float* in;
    float* out;
    if (row < BATCH * SEQN) {
        in = x + (size_t)row * DIM;
        out = xn + (size_t)row * DIM;
    } else {
        int r = row - BATCH * SEQN;
        in = ctx + (size_t)r * DIM;
        out = cn + (size_t)r * DIM;
    }
    int tid = threadIdx.x;               // 256 threads, 4 floats each
    float4 v4 = ((const float4*)in)[tid];
    float s  = v4.x + v4.y + v4.z + v4.w;
    float s2 = v4.x*v4.x + v4.y*v4.y + v4.z*v4.z + v4.w*v4.w;

    // warp reduce
    #pragma unroll
    for (int off = 16; off > 0; off >>= 1) {
        s  += __shfl_xor_sync(0xffffffffu, s,  off);
        s2 += __shfl_xor_sync(0xffffffffu, s2, off);
    }
    __shared__ float rs[8], rs2[8];
    int wid = tid >> 5, lid = tid & 31;
    if (lid == 0) { rs[wid] = s; rs2[wid] = s2; }
    __syncthreads();
    if (wid == 0) {
        s  = (lid < 8) ? rs[lid]  : 0.f;
        s2 = (lid < 8) ? rs2[lid] : 0.f;
        #pragma unroll
        for (int off = 4; off > 0; off >>= 1) {
            s  += __shfl_xor_sync(0xffffffffu, s,  off);
            s2 += __shfl_xor_sync(0xffffffffu, s2, off);
        }
        if (lid == 0) { rs[0] = s; rs2[0] = s2; }
    }
    __syncthreads();
    float mu  = rs[0] * (1.0f / DIM);
    float var = rs2[0] * (1.0f / DIM) - mu * mu;
    float inv = rsqrtf(var + LN_EPS);

    float4 w4 = ((const float4*)w)[tid];
    float4 b4 = ((const float4*)b)[tid];
    float4 o4;
    o4.x = (v4.x - mu) * inv * w4.x + b4.x;
    o4.y = (v4.y - mu) * inv * w4.y + b4.y;
    o4.z = (v4.z - mu) * inv * w4.z + b4.z;
    o4.w = (v4.w - mu) * inv * w4.w + b4.w;
    ((float4*)out)[tid] = o4;
}

// ---------------- SGEMM: C[M,N] = A[M,K] @ W[N,K]^T (+ bias[N]) ----------------
// K = N = DIM = 1024. 128x128 block tile, BK=16, 256 threads, 8x8 per thread.
#define GBM 128
#define GBN 128
#define GBK 16
#define SAPAD 132   // 128 + 4 padding

__global__ __launch_bounds__(256) void gemm_kernel(
    const float* __restrict__ A, const float* __restrict__ W,
    float* __restrict__ C, const float* __restrict__ bias)
{
    __shared__ float sA[GBK][SAPAD];
    __shared__ float sB[GBK][SAPAD];

    int tid = threadIdx.x;
    int m0 = blockIdx.y * GBM;
    int n0 = blockIdx.x * GBN;

    int tr = (tid >> 4) * 8;   // 0..120 (row within tile)
    int tc = (tid & 15) * 8;   // 0..120 (col within tile)

    int lr = tid >> 2;         // 0..63 (loader row)
    int lq = tid & 3;          // 0..3  (loader float4 within k-slab)

    float acc[8][8];
    #pragma unroll
    for (int i = 0; i < 8; i++)
        #pragma unroll
        for (int j = 0; j < 8; j++) acc[i][j] = 0.f;

    const float* Ap0 = A + (size_t)(m0 + lr)      * DIM + lq * 4;
    const float* Ap1 = A + (size_t)(m0 + lr + 64) * DIM + lq * 4;
    const float* Wp0 = W + (size_t)(n0 + lr)      * DIM + lq * 4;
    const float* Wp1 = W + (size_t)(n0 + lr + 64) * DIM + lq * 4;

    for (int k0 = 0; k0 < DIM; k0 += GBK) {
        float4 a0 = *(const float4*)(Ap0 + k0);
        float4 a1 = *(const float4*)(Ap1 + k0);
        float4 b0 = *(const float4*)(Wp0 + k0);
        float4 b1 = *(const float4*)(Wp1 + k0);
        __syncthreads();
        sA[lq*4+0][lr] = a0.x; sA[lq*4+1][lr] = a0.y;
        sA[lq*4+2][lr] = a0.z; sA[lq*4+3][lr] = a0.w;
        sA[lq*4+0][lr+64] = a1.x; sA[lq*4+1][lr+64] = a1.y;
        sA[lq*4+2][lr+64] = a1.z; sA[lq*4+3][lr+64] = a1.w;
        sB[lq*4+0][lr] = b0.x; sB[lq*4+1][lr] = b0.y;
        sB[lq*4+2][lr] = b0.z; sB[lq*4+3][lr] = b0.w;
        sB[lq*4+0][lr+64] = b1.x; sB[lq*4+1][lr+64] = b1.y;
        sB[lq*4+2][lr+64] = b1.z; sB[lq*4+3][lr+64] = b1.w;
        __syncthreads();

        #pragma unroll
        for (int kk = 0; kk < GBK; kk++) {
            float ar[8], br[8];
            *(float4*)&ar[0] = *(const float4*)&sA[kk][tr];
            *(float4*)&ar[4] = *(const float4*)&sA[kk][tr + 4];
            *(float4*)&br[0] = *(const float4*)&sB[kk][tc];
            *(float4*)&br[4] = *(const float4*)&sB[kk][tc + 4];
            #pragma unroll
            for (int i = 0; i < 8; i++)
                #pragma unroll
                for (int j = 0; j < 8; j++)
                    acc[i][j] += ar[i] * br[j];
        }
    }

    float bj[8];
    #pragma unroll
    for (int j = 0; j < 8; j++) bj[j] = bias ? bias[n0 + tc + j] : 0.f;

    #pragma unroll
    for (int i = 0; i < 8; i++) {
        float* Crow = C + (size_t)(m0 + tr + i) * DIM + n0 + tc;
        float4 o0, o1;
        o0.x = acc[i][0] + bj[0]; o0.y = acc[i][1] + bj[1];
        o0.z = acc[i][2] + bj[2]; o0.w = acc[i][3] + bj[3];
        o1.x = acc[i][4] + bj[4]; o1.y = acc[i][5] + bj[5];
        o1.z = acc[i][6] + bj[6]; o1.w = acc[i][7] + bj[7];
        *(float4*)(Crow)     = o0;
        *(float4*)(Crow + 4) = o1;
    }
}

// ---------------- Flash attention with alibi ----------------
// One block: 128 query rows of one (batch, head). 128 threads, 1 row/thread.
#define FBR 128
#define FBC 32

__global__ __launch_bounds__(128) void attn_kernel(const float* __restrict__ alibi)
{
    int bi = blockIdx.z;
    int h  = blockIdx.y;
    int i0 = blockIdx.x * FBR;
    int tid = threadIdx.x;

    __shared__ float sK[FBC][DH];          // 8 KB
    __shared__ float sV[FBC][DH];          // 8 KB
    __shared__ float sAl[FBR][FBC + 1];    // ~16.9 KB, padded

    float q[DH], o[DH];
    const size_t qbase = ((size_t)(bi * SEQN + i0 + tid)) * DIM + h * DH;
    #pragma unroll
    for (int d4 = 0; d4 < 16; d4++) {
        float4 t = *(const float4*)(g_q + qbase + d4 * 4);
        q[d4*4+0] = t.x * ATT_SCALE; q[d4*4+1] = t.y * ATT_SCALE;
        q[d4*4+2] = t.z * ATT_SCALE; q[d4*4+3] = t.w * ATT_SCALE;
    }
    #pragma unroll
    for (int d = 0; d < DH; d++) o[d] = 0.f;

    float mrow = -3.0e38f, l = 0.f;

    for (int j0 = 0; j0 < SEQM; j0 += FBC) {
        // K/V tiles (coalesced float4)
        const size_t kvbase = ((size_t)(bi * SEQM + j0)) * DIM + h * DH;
        #pragma unroll
        for (int it = 0; it < (FBC * (DH/4)) / 128; it++) {
            int idx = it * 128 + tid;
            int j = idx >> 4, d4 = idx & 15;
            *(float4*)&sK[j][d4*4] = *(const float4*)(g_k + kvbase + (size_t)j * DIM + d4 * 4);
            *(float4*)&sV[j][d4*4] = *(const float4*)(g_v + kvbase + (size_t)j * DIM + d4 * 4);
        }
        // alibi tile (coalesced float4 loads, scalar padded stores)
        const float* alb = alibi + ((size_t)h * SEQN + i0) * SEQM + j0;
        #pragma unroll
        for (int it = 0; it < (FBR * FBC / 4) / 128; it++) {
            int idx = it * 128 + tid;
            int r = idx >> 3, c4 = idx & 7;
            float4 t = *(const float4*)(alb + (size_t)r * SEQM + c4 * 4);
            sAl[r][c4*4+0] = t.x; sAl[r][c4*4+1] = t.y;
            sAl[r][c4*4+2] = t.z; sAl[r][c4*4+3] = t.w;
        }
        __syncthreads();

        float s[FBC];
        float tmax = -3.0e38f;
        #pragma unroll
        for (int j = 0; j < FBC; j++) {
            float a0 = 0.f, a1 = 0.f, a2 = 0.f, a3 = 0.f;
            #pragma unroll
            for (int d4 = 0; d4 < 16; d4++) {
                float4 kv = *(const float4*)&sK[j][d4*4];
                a0 += q[d4*4+0] * kv.x;
                a1 += q[d4*4+1] * kv.y;
                a2 += q[d4*4+2] * kv.z;
                a3 += q[d4*4+3] * kv.w;
            }
            float acc = (a0 + a1) + (a2 + a3) + sAl[tid][j];
            s[j] = acc;
            tmax = fmaxf(tmax, acc);
        }

        float mnew = fmaxf(mrow, tmax);
        float corr = __expf(mrow - mnew);
        l *= corr;
        #pragma unroll
        for (int d = 0; d < DH; d++) o[d] *= corr;

        float psum = 0.f;
        #pragma unroll
        for (int j = 0; j < FBC; j++) {
            s[j] = __expf(s[j] - mnew);
            psum += s[j];
        }
        l += psum;

        #pragma unroll
        for (int j = 0; j < FBC; j++) {
            float pj = s[j];
            #pragma unroll
            for (int d4 = 0; d4 < 16; d4++) {
                float4 vv = *(const float4*)&sV[j][d4*4];
                o[d4*4+0] += pj * vv.x;
                o[d4*4+1] += pj * vv.y;
                o[d4*4+2] += pj * vv.z;
                o[d4*4+3] += pj * vv.w;
            }
        }
        mrow = mnew;
        __syncthreads();
    }

    float inv = 1.f / l;
    #pragma unroll
    for (int d4 = 0; d4 < 16; d4++) {
        float4 t;
        t.x = o[d4*4+0] * inv; t.y = o[d4*4+1] * inv;
        t.z = o[d4*4+2] * inv; t.w = o[d4*4+3] * inv;
        *(float4*)(g_ao + qbase + d4 * 4) = t;
    }
}

// ---------------- launch ----------------
extern "C" void kernel_launch(void* const* d_in, const int* in_sizes, int n_in,
                              void* d_out, int out_size)
{
    const float* x     = (const float*)d_in[0];
    const float* ctx   = (const float*)d_in[1];
    const float* alibi = (const float*)d_in[2];
    const float* Wq    = (const float*)d_in[3];
    const float* Wk    = (const float*)d_in[4];
    const float* Wv    = (const float*)d_in[5];
    const float* Wo    = (const float*)d_in[6];
    const float* bo    = (const float*)d_in[7];
    const float* ln_w  = (const float*)d_in[8];
    const float* ln_b  = (const float*)d_in[9];
    float* out = (float*)d_out;

    float *p_xn, *p_cn, *p_q, *p_k, *p_v, *p_ao;
    cudaGetSymbolAddress((void**)&p_xn, g_xn);
    cudaGetSymbolAddress((void**)&p_cn, g_cn);
    cudaGetSymbolAddress((void**)&p_q,  g_q);
    cudaGetSymbolAddress((void**)&p_k,  g_k);
    cudaGetSymbolAddress((void**)&p_v,  g_v);
    cudaGetSymbolAddress((void**)&p_ao, g_ao);

    // LayerNorm x and context
    ln_kernel<<<BATCH * SEQN + BATCH * SEQM, 256>>>(x, ctx, ln_w, ln_b, p_xn, p_cn);

    // Projections: y = xn @ W^T
    dim3 ggrid(DIM / GBN, (BATCH * SEQN) / GBM);
    gemm_kernel<<<ggrid, 256>>>(p_xn, Wq, p_q, nullptr);
    gemm_kernel<<<ggrid, 256>>>(p_cn, Wk, p_k, nullptr);
    gemm_kernel<<<ggrid, 256>>>(p_cn, Wv, p_v, nullptr);

    // Flash attention with alibi
    dim3 agrid(SEQN / FBR, HEADS, BATCH);
    attn_kernel<<<agrid, 128>>>(alibi);

    // Output projection + bias -> d_out
    gemm_kernel<<<ggrid, 256>>>(p_ao, Wo, out, bo);
}

// round 2
// speedup vs baseline: 2.8668x; 2.8668x over previous
#include <cuda_runtime.h>
#include <math.h>
#include <stdint.h>

#define BATCH 2
#define SEQN 2048
#define SEQM 2048
#define DIM 1024
#define HEADS 16
#define DH 64
#define ATT_SCALE 0.125f
#define LN_EPS 1e-5f

// ---------------- scratch (static device memory; no allocation) ----------------
__device__ float g_xn[BATCH * SEQN * DIM];
__device__ float g_cn[BATCH * SEQM * DIM];
__device__ float g_q [BATCH * SEQN * DIM];
__device__ float g_k [BATCH * SEQM * DIM];
__device__ float g_v [BATCH * SEQM * DIM];
__device__ float g_ao[BATCH * SEQN * DIM];

// ---------------- helpers ----------------
__device__ __forceinline__ uint32_t f2tf(float f) {
    uint32_t r;
    asm("cvt.rna.tf32.f32 %0, %1;" : "=r"(r) : "f"(f));
    return r;
}

__device__ __forceinline__ void mma_tf32(float* c, const uint32_t* a, uint32_t b0, uint32_t b1) {
    asm volatile(
        "mma.sync.aligned.m16n8k8.row.col.f32.tf32.tf32.f32 "
        "{%0,%1,%2,%3}, {%4,%5,%6,%7}, {%8,%9}, {%0,%1,%2,%3};\n"
        : "+f"(c[0]), "+f"(c[1]), "+f"(c[2]), "+f"(c[3])
        : "r"(a[0]), "r"(a[1]), "r"(a[2]), "r"(a[3]), "r"(b0), "r"(b1));
}

// ---------------- LayerNorm: one block per row ----------------
__global__ __launch_bounds__(256) void ln_kernel(
    const float* __restrict__ x, const float* __restrict__ ctx,
    const float* __restrict__ w, const float* __restrict__ b,
    float* __restrict__ xn, float* __restrict__ cn)
{
    int row = blockIdx.x;
    const float* in;
    float* out;
    if (row < BATCH * SEQN) {
        in = x + (size_t)row * DIM;
        out = xn + (size_t)row * DIM;
    } else {
        int r = row - BATCH * SEQN;
        in = ctx + (size_t)r * DIM;
        out = cn + (size_t)r * DIM;
    }
    int tid = threadIdx.x;
    float4 v4 = ((const float4*)in)[tid];
    float s  = v4.x + v4.y + v4.z + v4.w;
    float s2 = v4.x*v4.x + v4.y*v4.y + v4.z*v4.z + v4.w*v4.w;

    #pragma unroll
    for (int off = 16; off > 0; off >>= 1) {
        s  += __shfl_xor_sync(0xffffffffu, s,  off);
        s2 += __shfl_xor_sync(0xffffffffu, s2, off);
    }
    __shared__ float rs[8], rs2[8];
    int wid = tid >> 5, lid = tid & 31;
    if (lid == 0) { rs[wid] = s; rs2[wid] = s2; }
    __syncthreads();
    if (wid == 0) {
        s  = (lid < 8) ? rs[lid]  : 0.f;
        s2 = (lid < 8) ? rs2[lid] : 0.f;
        #pragma unroll
        for (int off = 4; off > 0; off >>= 1) {
            s  += __shfl_xor_sync(0xffffffffu, s,  off);
            s2 += __shfl_xor_sync(0xffffffffu, s2, off);
        }
        if (lid == 0) { rs[0] = s; rs2[0] = s2; }
    }
    __syncthreads();
    float mu  = rs[0] * (1.0f / DIM);
    float var = rs2[0] * (1.0f / DIM) - mu * mu;
    float inv = rsqrtf(var + LN_EPS);

    float4 w4 = ((const float4*)w)[tid];
    float4 b4 = ((const float4*)b)[tid];
    float4 o4;
    o4.x = (v4.x - mu) * inv * w4.x + b4.x;
    o4.y = (v4.y - mu) * inv * w4.y + b4.y;
    o4.z = (v4.z - mu) * inv * w4.z + b4.z;
    o4.w = (v4.w - mu) * inv * w4.w + b4.w;
    ((float4*)out)[tid] = o4;
}

// ---------------- tf32 GEMM: C[M,N] = A[M,K] @ W[N,K]^T (+bias) ----------------
// 128x128 tile, BK=32, 256 threads (8 warps, 2x4), warp tile 64x32.
#define SAS 36   // smem row stride (32 + 4 pad) -> conflict-free fragment loads

__global__ __launch_bounds__(256) void gemm_tf32(
    const float* __restrict__ A, const float* __restrict__ W,
    float* __restrict__ C, const float* __restrict__ bias)
{
    __shared__ uint32_t sA[128 * SAS];
    __shared__ uint32_t sB[128 * SAS];

    int tid = threadIdx.x;
    int lane = tid & 31, w = tid >> 5;
    int g = lane >> 2, q = lane & 3;
    int wm = (w >> 2) * 64, wn = (w & 3) * 32;
    int m0 = blockIdx.y * 128, n0 = blockIdx.x * 128;

    int lr = tid >> 1;          // 0..127
    int lk = (tid & 1) * 16;    // 0 or 16

    const float* Ap = A + (size_t)(m0 + lr) * DIM + lk;
    const float* Wp = W + (size_t)(n0 + lr) * DIM + lk;

    float acc[4][4][4];
    #pragma unroll
    for (int mt = 0; mt < 4; mt++)
        #pragma unroll
        for (int nt = 0; nt < 4; nt++)
            #pragma unroll
            for (int i = 0; i < 4; i++) acc[mt][nt][i] = 0.f;

    for (int k0 = 0; k0 < DIM; k0 += 32) {
        float4 av[4], wv[4];
        #pragma unroll
        for (int i = 0; i < 4; i++) {
            av[i] = *(const float4*)(Ap + k0 + i * 4);
            wv[i] = *(const float4*)(Wp + k0 + i * 4);
        }
        __syncthreads();
        #pragma unroll
        for (int i = 0; i < 4; i++) {
            uint32_t* d = &sA[lr * SAS + lk + i * 4];
            d[0] = f2tf(av[i].x); d[1] = f2tf(av[i].y);
            d[2] = f2tf(av[i].z); d[3] = f2tf(av[i].w);
            uint32_t* e = &sB[lr * SAS + lk + i * 4];
            e[0] = f2tf(wv[i].x); e[1] = f2tf(wv[i].y);
            e[2] = f2tf(wv[i].z); e[3] = f2tf(wv[i].w);
        }
        __syncthreads();

        #pragma unroll
        for (int ks = 0; ks < 4; ks++) {
            uint32_t af[4][4], bf[4][2];
            #pragma unroll
            for (int mt = 0; mt < 4; mt++) {
                int r = wm + mt * 16 + g, c = ks * 8 + q;
                af[mt][0] = sA[r * SAS + c];
                af[mt][1] = sA[(r + 8) * SAS + c];
                af[mt][2] = sA[r * SAS + c + 4];
                af[mt][3] = sA[(r + 8) * SAS + c + 4];
            }
            #pragma unroll
            for (int nt = 0; nt < 4; nt++) {
                int r = wn + nt * 8 + g, c = ks * 8 + q;
                bf[nt][0] = sB[r * SAS + c];
                bf[nt][1] = sB[r * SAS + c + 4];
            }
            #pragma unroll
            for (int mt = 0; mt < 4; mt++)
                #pragma unroll
                for (int nt = 0; nt < 4; nt++)
                    mma_tf32(acc[mt][nt], af[mt], bf[nt][0], bf[nt][1]);
        }
    }

    #pragma unroll
    for (int mt = 0; mt < 4; mt++) {
        #pragma unroll
        for (int nt = 0; nt < 4; nt++) {
            int row = m0 + wm + mt * 16 + g;
            int col = n0 + wn + nt * 8 + 2 * q;
            float b0 = bias ? bias[col] : 0.f;
            float b1 = bias ? bias[col + 1] : 0.f;
            float2 o0, o1;
            o0.x = acc[mt][nt][0] + b0; o0.y = acc[mt][nt][1] + b1;
            o1.x = acc[mt][nt][2] + b0; o1.y = acc[mt][nt][3] + b1;
            *(float2*)&C[(size_t)row * DIM + col] = o0;
            *(float2*)&C[(size_t)(row + 8) * DIM + col] = o1;
        }
    }
}

// ---------------- tensor-core flash attention with alibi ----------------
// Block: 128 q-rows of one (b,h). 256 threads = 8 warps, warp owns 16 rows.
// KV tile = 64. Alibi is loaded directly into S accumulators (coalesced float2).
#define KST 68   // sK / sPQ row stride
#define VST 72   // sV row stride

__global__ __launch_bounds__(256) void attn_tc(const float* __restrict__ alibi)
{
    extern __shared__ uint32_t dsm[];
    uint32_t* sK  = dsm;                 // [64][KST]
    uint32_t* sV  = dsm + 64 * KST;      // [64][VST]
    uint32_t* sPQ = dsm + 64 * KST + 64 * VST;  // [128][KST] (Q, then P per warp)

    int tid = threadIdx.x;
    int lane = tid & 31, w = tid >> 5;
    int g = lane >> 2, q = lane & 3;
    int bi = blockIdx.z, h = blockIdx.y, i0 = blockIdx.x * 128;

    // stage Q (scaled, tf32)
    {
        int r = tid >> 1;
        int cb = (tid & 1) * 32;
        const float* qp = g_q + ((size_t)(bi * SEQN + i0 + r)) * DIM + h * DH + cb;
        #pragma unroll
        for (int i = 0; i < 8; i++) {
            float4 t = *(const float4*)(qp + i * 4);
            uint32_t* d = &sPQ[r * KST + cb + i * 4];
            d[0] = f2tf(t.x * ATT_SCALE); d[1] = f2tf(t.y * ATT_SCALE);
            d[2] = f2tf(t.z * ATT_SCALE); d[3] = f2tf(t.w * ATT_SCALE);
        }
    }
    __syncthreads();

    uint32_t qf[8][4];
    #pragma unroll
    for (int ks = 0; ks < 8; ks++) {
        int r = w * 16 + g, c = ks * 8 + q;
        qf[ks][0] = sPQ[r * KST + c];
        qf[ks][1] = sPQ[(r + 8) * KST + c];
        qf[ks][2] = sPQ[r * KST + c + 4];
        qf[ks][3] = sPQ[(r + 8) * KST + c + 4];
    }

    float o[8][4];
    #pragma unroll
    for (int nt = 0; nt < 8; nt++)
        #pragma unroll
        for (int i = 0; i < 4; i++) o[nt][i] = 0.f;
    float m0r = -3.0e38f, m1r = -3.0e38f, l0 = 0.f, l1 = 0.f;

    const size_t alr0 = ((size_t)h * SEQN + (i0 + w * 16 + g)) * (size_t)SEQM + 2 * q;
    const size_t alr1 = alr0 + 8 * (size_t)SEQM;

    int kr = tid >> 2, kc = tid & 3;
    const float* kbase = g_k + ((size_t)(bi * SEQM + kr)) * DIM + h * DH;
    const float* vbase = g_v + ((size_t)(bi * SEQM + kr)) * DIM + h * DH;

    for (int j0 = 0; j0 < SEQM; j0 += 64) {
        // prefetch K/V tile
        float4 kv4[4], vv4[4];
        #pragma unroll
        for (int i = 0; i < 4; i++) {
            kv4[i] = *(const float4*)(kbase + (size_t)j0 * DIM + kc * 4 + i * 16);
            vv4[i] = *(const float4*)(vbase + (size_t)j0 * DIM + kc * 4 + i * 16);
        }
        __syncthreads();
        #pragma unroll
        for (int i = 0; i < 4; i++) {
            int c = kc * 4 + i * 16;
            uint32_t* dk = &sK[kr * KST + c];
            dk[0] = f2tf(kv4[i].x); dk[1] = f2tf(kv4[i].y);
            dk[2] = f2tf(kv4[i].z); dk[3] = f2tf(kv4[i].w);
            uint32_t* dv = &sV[kr * VST + c];
            dv[0] = f2tf(vv4[i].x); dv[1] = f2tf(vv4[i].y);
            dv[2] = f2tf(vv4[i].z); dv[3] = f2tf(vv4[i].w);
        }
        __syncthreads();

        // S = alibi + Q K^T (scaled)
        float s[8][4];
        #pragma unroll
        for (int nt = 0; nt < 8; nt++) {
            float2 a0 = *(const float2*)(alibi + alr0 + j0 + nt * 8);
            float2 a1 = *(const float2*)(alibi + alr1 + j0 + nt * 8);
            s[nt][0] = a0.x; s[nt][1] = a0.y; s[nt][2] = a1.x; s[nt][3] = a1.y;
            #pragma unroll
            for (int ks = 0; ks < 8; ks++) {
                uint32_t b0 = sK[(nt * 8 + g) * KST + ks * 8 + q];
                uint32_t b1 = sK[(nt * 8 + g) * KST + ks * 8 + q + 4];
                mma_tf32(s[nt], qf[ks], b0, b1);
            }
        }

        // row max (2 rows per thread: g, g+8)
        float tm0 = -3.0e38f, tm1 = -3.0e38f;
        #pragma unroll
        for (int nt = 0; nt < 8; nt++) {
            tm0 = fmaxf(tm0, fmaxf(s[nt][0], s[nt][1]));
            tm1 = fmaxf(tm1, fmaxf(s[nt][2], s[nt][3]));
        }
        tm0 = fmaxf(tm0, __shfl_xor_sync(0xffffffffu, tm0, 1));
        tm0 = fmaxf(tm0, __shfl_xor_sync(0xffffffffu, tm0, 2));
        tm1 = fmaxf(tm1, __shfl_xor_sync(0xffffffffu, tm1, 1));
        tm1 = fmaxf(tm1, __shfl_xor_sync(0xffffffffu, tm1, 2));

        float mn0 = fmaxf(m0r, tm0), mn1 = fmaxf(m1r, tm1);
        float c0 = __expf(m0r - mn0), c1 = __expf(m1r - mn1);
        l0 *= c0; l1 *= c1;
        #pragma unroll
        for (int nt = 0; nt < 8; nt++) {
            o[nt][0] *= c0; o[nt][1] *= c0;
            o[nt][2] *= c1; o[nt][3] *= c1;
        }
        m0r = mn0; m1r = mn1;

        float ps0 = 0.f, ps1 = 0.f;
        int prow = w * 16 + g;
        #pragma unroll
        for (int nt = 0; nt < 8; nt++) {
            float p0 = __expf(s[nt][0] - mn0);
            float p1 = __expf(s[nt][1] - mn0);
            float p2 = __expf(s[nt][2] - mn1);
            float p3 = __expf(s[nt][3] - mn1);
            ps0 += p0 + p1; ps1 += p2 + p3;
            int col = nt * 8 + 2 * q;
            sPQ[prow * KST + col]     = f2tf(p0);
            sPQ[prow * KST + col + 1] = f2tf(p1);
            sPQ[(prow + 8) * KST + col]     = f2tf(p2);
            sPQ[(prow + 8) * KST + col + 1] = f2tf(p3);
        }
        ps0 += __shfl_xor_sync(0xffffffffu, ps0, 1);
        ps0 += __shfl_xor_sync(0xffffffffu, ps0, 2);
        ps1 += __shfl_xor_sync(0xffffffffu, ps1, 1);
        ps1 += __shfl_xor_sync(0xffffffffu, ps1, 2);
        l0 += ps0; l1 += ps1;

        __syncwarp();

        // O += P V
        #pragma unroll
        for (int ks = 0; ks < 8; ks++) {
            uint32_t af[4];
            af[0] = sPQ[prow * KST + ks * 8 + q];
            af[1] = sPQ[(prow + 8) * KST + ks * 8 + q];
            af[2] = sPQ[prow * KST + ks * 8 + q + 4];
            af[3] = sPQ[(prow + 8) * KST + ks * 8 + q + 4];
            #pragma unroll
            for (int nt = 0; nt < 8; nt++) {
                uint32_t b0 = sV[(ks * 8 + q) * VST + nt * 8 + g];
                uint32_t b1 = sV[(ks * 8 + q + 4) * VST + nt * 8 + g];
                mma_tf32(o[nt], af, b0, b1);
            }
        }
    }

    float inv0 = 1.f / l0, inv1 = 1.f / l1;
    size_t orow = (size_t)(bi * SEQN + i0 + w * 16 + g) * DIM + h * DH;
    #pragma unroll
    for (int nt = 0; nt < 8; nt++) {
        int col = nt * 8 + 2 * q;
        float2 t0, t1;
        t0.x = o[nt][0] * inv0; t0.y = o[nt][1] * inv0;
        t1.x = o[nt][2] * inv1; t1.y = o[nt][3] * inv1;
        *(float2*)&g_ao[orow + col] = t0;
        *(float2*)&g_ao[orow + 8 * DIM + col] = t1;
    }
}

// ---------------- launch ----------------
extern "C" void kernel_launch(void* const* d_in, const int* in_sizes, int n_in,
                              void* d_out, int out_size)
{
    const float* x     = (const float*)d_in[0];
    const float* ctx   = (const float*)d_in[1];
    const float* alibi = (const float*)d_in[2];
    const float* Wq    = (const float*)d_in[3];
    const float* Wk    = (const float*)d_in[4];
    const float* Wv    = (const float*)d_in[5];
    const float* Wo    = (const float*)d_in[6];
    const float* bo    = (const float*)d_in[7];
    const float* ln_w  = (const float*)d_in[8];
    const float* ln_b  = (const float*)d_in[9];
    float* out = (float*)d_out;

    float *p_xn, *p_cn, *p_q, *p_k, *p_v, *p_ao;
    cudaGetSymbolAddress((void**)&p_xn, g_xn);
    cudaGetSymbolAddress((void**)&p_cn, g_cn);
    cudaGetSymbolAddress((void**)&p_q,  g_q);
    cudaGetSymbolAddress((void**)&p_k,  g_k);
    cudaGetSymbolAddress((void**)&p_v,  g_v);
    cudaGetSymbolAddress((void**)&p_ao, g_ao);

    // LayerNorm x and context
    ln_kernel<<<BATCH * SEQN + BATCH * SEQM, 256>>>(x, ctx, ln_w, ln_b, p_xn, p_cn);

    // Projections: y = xn @ W^T
    dim3 ggrid(DIM / 128, (BATCH * SEQN) / 128);
    gemm_tf32<<<ggrid, 256>>>(p_xn, Wq, p_q, nullptr);
    gemm_tf32<<<ggrid, 256>>>(p_cn, Wk, p_k, nullptr);
    gemm_tf32<<<ggrid, 256>>>(p_cn, Wv, p_v, nullptr);

    // Flash attention with alibi (tensor cores)
    static const int attn_smem = (64 * KST + 64 * VST + 128 * KST) * 4;
    cudaFuncSetAttribute(attn_tc, cudaFuncAttributeMaxDynamicSharedMemorySize, attn_smem);
    dim3 agrid(SEQN / 128, HEADS, BATCH);
    attn_tc<<<agrid, 256, attn_smem>>>(alibi);

    // Output projection + bias -> d_out
    gemm_tf32<<<ggrid, 256>>>(p_ao, Wo, out, bo);
}